// round 4
// baseline (speedup 1.0000x reference)
#include <cuda_runtime.h>
#include <cuda_fp16.h>

// GNNGUARD: per-edge cosine similarity + threshold + row-L1-normalize + exp.
// Output layout (float32): [row (E) | col (E) | exp(norm_score) (E)]
//
// Pass 1 (norm_kernel):  inv[i] = 1/max(||x_i||,eps); xh[i] = fp16(x_i*inv)
//                        stored with a 128B row stride (padded) so each row
//                        occupies exactly ONE cache line. rowsum[i] = 0.
// Pass 2 (edge_kernel):  8 lanes / 2 edges. For each edge, 6 lanes load the
//                        whole 96B fp16 row in ONE uint4 instruction -> one
//                        L1tex wavefront per row (2 per edge). fp32-accum dot,
//                        near-threshold edges recomputed in fp32 from raw x,
//                        threshold, atomic row-sum, edge_index floats to out.
// Pass 3 (final_kernel): out[2E+i] = exp(score/denom), 4 edges/thread.

#define N_NODES_MAX 100000
#define N_EDGES_MAX 1600000
#define D_FEAT 48
#define ROW_H 64          // padded fp16 row stride (halves) = 128 bytes
#define EPS 1e-8f
#define THRESH 0.1f
#define BAND 1.5e-3f

__device__ float g_inv[N_NODES_MAX];
__device__ float g_rowsum[N_NODES_MAX];
__device__ float g_score[N_EDGES_MAX];
__device__ __align__(16) __half g_xh[(size_t)N_NODES_MAX * ROW_H];

__device__ __forceinline__ float dot4(float4 a, float4 b) {
    float s = a.x * b.x;
    s = fmaf(a.y, b.y, s);
    s = fmaf(a.z, b.z, s);
    s = fmaf(a.w, b.w, s);
    return s;
}

__device__ __forceinline__ float dot_h2(unsigned ua, unsigned ub, float s) {
    __half2 ha = *reinterpret_cast<__half2*>(&ua);
    __half2 hb = *reinterpret_cast<__half2*>(&ub);
    float2 fa = __half22float2(ha);
    float2 fb = __half22float2(hb);
    s = fmaf(fa.x, fb.x, s);
    s = fmaf(fa.y, fb.y, s);
    return s;
}

__device__ __forceinline__ float dot_u4(uint4 a, uint4 b) {
    float s = 0.0f;
    s = dot_h2(a.x, b.x, s);
    s = dot_h2(a.y, b.y, s);
    s = dot_h2(a.z, b.z, s);
    s = dot_h2(a.w, b.w, s);
    return s;
}

// 8 lanes per row, 2 rows per group (rows g and g+nhalf) for MLP.
__global__ void norm_kernel(const float* __restrict__ x, int n) {
    int nhalf = (n + 1) >> 1;
    int g = blockIdx.x * (blockDim.x >> 3) + (threadIdx.x >> 3);
    int l = threadIdx.x & 7;
    if (g >= nhalf) return;

    int rows[2] = {g, g + nhalf};
    int cnt = (rows[1] < n) ? 2 : 1;

    float4 v0[2], v1[2];
#pragma unroll
    for (int j = 0; j < 2; j++) {
        if (j >= cnt) break;
        const float4* __restrict__ xr = (const float4*)(x + (size_t)rows[j] * D_FEAT);
        v0[j] = __ldg(&xr[l]);
        if (l < 4) v1[j] = __ldg(&xr[8 + l]);
    }

#pragma unroll
    for (int j = 0; j < 2; j++) {
        if (j >= cnt) break;
        int row = rows[j];
        float ss = dot4(v0[j], v0[j]);
        if (l < 4) ss += dot4(v1[j], v1[j]);
        ss += __shfl_xor_sync(0xffffffffu, ss, 4, 8);
        ss += __shfl_xor_sync(0xffffffffu, ss, 2, 8);
        ss += __shfl_xor_sync(0xffffffffu, ss, 1, 8);
        float inv = 1.0f / fmaxf(sqrtf(ss), EPS);
        if (l == 0) {
            g_inv[row] = inv;
            g_rowsum[row] = 0.0f;
        }
        // write padded fp16 normalized row (stride 128B, data in halves [0,48))
        __half* hr = g_xh + (size_t)row * ROW_H;
        {
            __half2 h01 = __floats2half2_rn(v0[j].x * inv, v0[j].y * inv);
            __half2 h23 = __floats2half2_rn(v0[j].z * inv, v0[j].w * inv);
            uint2 w;
            w.x = *reinterpret_cast<unsigned*>(&h01);
            w.y = *reinterpret_cast<unsigned*>(&h23);
            *reinterpret_cast<uint2*>(hr + 4 * l) = w;
        }
        if (l < 4) {
            __half2 h01 = __floats2half2_rn(v1[j].x * inv, v1[j].y * inv);
            __half2 h23 = __floats2half2_rn(v1[j].z * inv, v1[j].w * inv);
            uint2 w;
            w.x = *reinterpret_cast<unsigned*>(&h01);
            w.y = *reinterpret_cast<unsigned*>(&h23);
            *reinterpret_cast<uint2*>(hr + 32 + 4 * l) = w;
        }
    }
}

// Exact fp32 cosine from raw x for near-threshold edges (8-lane group).
__device__ __forceinline__ float exact_cos(const float* __restrict__ x,
                                           int r, int c, int l) {
    const float4* __restrict__ af = (const float4*)(x + (size_t)r * D_FEAT);
    const float4* __restrict__ bf = (const float4*)(x + (size_t)c * D_FEAT);
    float d = dot4(__ldg(&af[l]), __ldg(&bf[l]));
    if (l < 4) d += dot4(__ldg(&af[8 + l]), __ldg(&bf[8 + l]));
    d += __shfl_xor_sync(0xffffffffu, d, 4, 8);
    d += __shfl_xor_sync(0xffffffffu, d, 2, 8);
    d += __shfl_xor_sync(0xffffffffu, d, 1, 8);
    return d * g_inv[r] * g_inv[c];
}

// 8 lanes handle 2 edges. 6 lanes load a whole 96B row with one uint4 each.
__global__ void edge_kernel(const float* __restrict__ x,
                            const int* __restrict__ ei,
                            float* __restrict__ out, int E) {
    int g = blockIdx.x * (blockDim.x >> 3) + (threadIdx.x >> 3);
    int l = threadIdx.x & 7;
    int e0 = 2 * g;
    int e1 = e0 + 1;
    if (e0 >= E) return;
    bool has1 = (e1 < E);

    int r0 = __ldg(&ei[e0]);
    int c0 = __ldg(&ei[E + e0]);
    int r1 = has1 ? __ldg(&ei[e1]) : 0;
    int c1 = has1 ? __ldg(&ei[E + e1]) : 0;

    const uint4* __restrict__ pa0 = (const uint4*)(g_xh + (size_t)r0 * ROW_H);
    const uint4* __restrict__ pb0 = (const uint4*)(g_xh + (size_t)c0 * ROW_H);
    const uint4* __restrict__ pa1 = (const uint4*)(g_xh + (size_t)r1 * ROW_H);
    const uint4* __restrict__ pb1 = (const uint4*)(g_xh + (size_t)c1 * ROW_H);

    uint4 z = make_uint4(0u, 0u, 0u, 0u);
    uint4 A0 = (l < 6) ? pa0[l] : z;
    uint4 B0 = (l < 6) ? pb0[l] : z;
    uint4 A1 = (l < 6 && has1) ? pa1[l] : z;
    uint4 B1 = (l < 6 && has1) ? pb1[l] : z;

    float s0 = dot_u4(A0, B0);
    float s1 = dot_u4(A1, B1);
    s0 += __shfl_xor_sync(0xffffffffu, s0, 4, 8);
    s1 += __shfl_xor_sync(0xffffffffu, s1, 4, 8);
    s0 += __shfl_xor_sync(0xffffffffu, s0, 2, 8);
    s1 += __shfl_xor_sync(0xffffffffu, s1, 2, 8);
    s0 += __shfl_xor_sync(0xffffffffu, s0, 1, 8);
    s1 += __shfl_xor_sync(0xffffffffu, s1, 1, 8);
    // all 8 lanes hold both approximate cosines

    if (fabsf(s0 - THRESH) < BAND) s0 = exact_cos(x, r0, c0, l);
    if (has1 && fabsf(s1 - THRESH) < BAND) s1 = exact_cos(x, r1, c1, l);

    s0 = (s0 < THRESH) ? 0.0f : s0;
    s1 = (s1 < THRESH) ? 0.0f : s1;

    if (l == 0) {
        g_score[e0] = s0;
        if (s0 != 0.0f) atomicAdd(&g_rowsum[r0], s0);
    } else if (l == 1 && has1) {
        g_score[e1] = s1;
        if (s1 != 0.0f) atomicAdd(&g_rowsum[r1], s1);
    } else if (l == 2) {
        out[e0] = (float)r0;
    } else if (l == 3 && has1) {
        out[e1] = (float)r1;
    } else if (l == 4) {
        out[E + e0] = (float)c0;
    } else if (l == 5 && has1) {
        out[E + e1] = (float)c1;
    }
}

__device__ __forceinline__ float dn(float rs) { return (rs == 0.0f) ? 1.0f : rs; }

// 4 edges per thread, vectorized.
__global__ void final_kernel(const int* __restrict__ ei,
                             float* __restrict__ out, int E) {
    int base = (blockIdx.x * blockDim.x + threadIdx.x) * 4;
    if (base >= E) return;
    if (base + 4 <= E) {
        int4 r4 = *(const int4*)(ei + base);
        float4 s4 = *(const float4*)(g_score + base);
        float4 o;
        o.x = __expf(s4.x / dn(g_rowsum[r4.x]));
        o.y = __expf(s4.y / dn(g_rowsum[r4.y]));
        o.z = __expf(s4.z / dn(g_rowsum[r4.z]));
        o.w = __expf(s4.w / dn(g_rowsum[r4.w]));
        *(float4*)(out + 2 * (size_t)E + base) = o;
    } else {
        for (int i = base; i < E; i++) {
            float rs = g_rowsum[__ldg(&ei[i])];
            out[2 * (size_t)E + i] = __expf(g_score[i] / dn(rs));
        }
    }
}

extern "C" void kernel_launch(void* const* d_in, const int* in_sizes, int n_in,
                              void* d_out, int out_size) {
    const float* x  = (const float*)d_in[0];
    const int*   ei = (const int*)d_in[1];
    float* out = (float*)d_out;

    int n = in_sizes[0] / D_FEAT;   // 100000
    int E = in_sizes[1] / 2;        // 1600000

    int nhalf = (n + 1) >> 1;
    norm_kernel<<<(nhalf + 31) / 32, 256>>>(x, n);
    // 256 threads = 32 groups = 64 edges per block
    edge_kernel<<<(E + 63) / 64, 256>>>(x, ei, out, E);
    final_kernel<<<((E + 3) / 4 + 255) / 256, 256>>>(ei, out, E);
}